// round 6
// baseline (speedup 1.0000x reference)
#include <cuda_runtime.h>

#define NN 256
#define TT 1500
#define R 4
#define CT (32 * R)                 // 128 steps per warp-chunk
#define NCHUNK ((TT + CT - 1) / CT) // 12 (tail: lanes 0..22 active, whole lanes)

// q[s][n][t] = 0.3125 - 0.075*g_max[s][n]*sat(u_s[n][t]); a_ij(t) = q0+q1
__device__ float g_q[2][NN * TT];

__global__ __launch_bounds__(256) void prep_kernel(const float* __restrict__ u0,
                                                   const float* __restrict__ u1,
                                                   const float* __restrict__ ksyn) {
    int idx = blockIdx.x * 256 + threadIdx.x;
    if (idx >= NN * TT) return;
    int n = idx / TT;
    float k0 = ksyn[n];
    float c0 = 0.075f * k0 / (20.0f - 2.0f * k0);
    g_q[0][idx] = 0.3125f - c0 * __saturatef(u0[idx]);
    float k1 = ksyn[NN + n];
    float c1 = 0.075f * k1 / (20.0f - 2.0f * k1);
    g_q[1][idx] = 0.3125f - c1 * __saturatef(u1[idx]);
}

// One cell's 128-step chunk: local compose (R=4), 3-level truncated scan
// (window 32 steps; dropped terms <= 0.625^32 ~ 2.9e-7), replay + store.
__device__ __forceinline__ void cell_chunk(const float4 x, const float4 y,
                                           const bool act, const int lane,
                                           float& carry, float* __restrict__ o,
                                           const int t) {
    float a0, a1, a2, a3, b0, b1, b2, b3, A, B;
    if (act) {
        a0 = x.x + y.x;  b0 = fmaf(-20.0f, a0, 12.5f);
        a1 = x.y + y.y;  b1 = fmaf(-20.0f, a1, 12.5f);
        a2 = x.z + y.z;  b2 = fmaf(-20.0f, a2, 12.5f);
        a3 = x.w + y.w;  b3 = fmaf(-20.0f, a3, 12.5f);
        A = a0; B = b0;
        B = fmaf(a1, B, b1); A *= a1;
        B = fmaf(a2, B, b2); A *= a2;
        B = fmaf(a3, B, b3); A *= a3;
    } else {
        A = 1.0f; B = 0.0f;
    }

    #pragma unroll
    for (int d = 1; d <= 4; d <<= 1) {
        float Au = __shfl_up_sync(0xffffffffu, A, d);
        float Bu = __shfl_up_sync(0xffffffffu, B, d);
        if (lane >= d) { B = fmaf(A, Bu, B); A *= Au; }
    }

    float Ae = __shfl_up_sync(0xffffffffu, A, 1);
    float Be = __shfl_up_sync(0xffffffffu, B, 1);
    float v = (lane == 0) ? carry : fmaf(Ae, carry, Be);

    float Al = __shfl_sync(0xffffffffu, A, 31);
    float Bl = __shfl_sync(0xffffffffu, B, 31);
    carry = fmaf(Al, carry, Bl);

    if (act) {
        float4 r;
        v = fmaf(a0, v, b0); r.x = v;
        v = fmaf(a1, v, b1); r.y = v;
        v = fmaf(a2, v, b2); r.z = v;
        v = fmaf(a3, v, b3); r.w = v;
        *(float4*)(o + t) = r;
    }
}

// Warp owns a 2x2 cell tile: 4 row-loads feed 4 cell-chunks (load:store 1:1).
__global__ __launch_bounds__(512) void sim_kernel(float* __restrict__ out) {
    const int lane = threadIdx.x & 31;
    const int w    = threadIdx.x >> 5;            // 0..15
    const int i0 = blockIdx.y * 8 + (w >> 2) * 2; // warp tile origin
    const int j0 = blockIdx.x * 8 + (w & 3) * 2;

    const float* __restrict__ qi0 = g_q[0] + i0 * TT;
    const float* __restrict__ qi1 = qi0 + TT;
    const float* __restrict__ qj0 = g_q[1] + j0 * TT;
    const float* __restrict__ qj1 = qj0 + TT;

    float* __restrict__ o00 = out + (i0 * NN + j0) * TT;
    float* __restrict__ o01 = o00 + TT;
    float* __restrict__ o10 = o00 + NN * TT;
    float* __restrict__ o11 = o10 + TT;

    float c00 = 0.0f, c01 = 0.0f, c10 = 0.0f, c11 = 0.0f;

    for (int c = 0; c < NCHUNK; c++) {
        const int t = c * CT + lane * R;
        const bool act = (t < TT);

        float4 x0, x1, y0, y1;
        if (act) {
            x0 = *(const float4*)(qi0 + t);
            x1 = *(const float4*)(qi1 + t);
            y0 = *(const float4*)(qj0 + t);
            y1 = *(const float4*)(qj1 + t);
        }

        cell_chunk(x0, y0, act, lane, c00, o00, t);
        cell_chunk(x0, y1, act, lane, c01, o01, t);
        cell_chunk(x1, y0, act, lane, c10, o10, t);
        cell_chunk(x1, y1, act, lane, c11, o11, t);
    }
}

extern "C" void kernel_launch(void* const* d_in, const int* in_sizes, int n_in,
                              void* d_out, int out_size) {
    const float* u0   = (const float*)d_in[0];   // u_pre_0 (N,T)
    const float* u1   = (const float*)d_in[1];   // u_pre_1 (N,T)
    const float* ksyn = (const float*)d_in[2];   // k_syn (2,N)
    float* out = (float*)d_out;                  // (N,N,T) fp32

    prep_kernel<<<(NN * TT + 255) / 256, 256>>>(u0, u1, ksyn);

    dim3 grid(NN / 8, NN / 8);                   // 32 x 32 blocks, 512 thr
    sim_kernel<<<grid, 512>>>(out);
}

// round 7
// speedup vs baseline: 1.0585x; 1.0585x over previous
#include <cuda_runtime.h>

#define NN 256
#define TT 1500
#define R 8
#define CT (32 * R)                  // 256 steps per warp-chunk
#define NCHUNK ((TT + CT - 1) / CT)  // 6 (tail chunk: 220 steps)

// q[s][n][t] = 0.3125 - 0.075*g_max[s][n]*sat(u_s[n][t]); a_ij(t) = q0+q1.
// +8 pad per plane: tail lane may over-read 4 floats past the last row
// (values never stored; .bss zeros keep it deterministic).
__device__ float g_q[2][NN * TT + 8];

__global__ __launch_bounds__(256) void prep_kernel(const float* __restrict__ u0,
                                                   const float* __restrict__ u1,
                                                   const float* __restrict__ ksyn) {
    int idx = blockIdx.x * 256 + threadIdx.x;
    if (idx >= NN * TT) return;
    int n = idx / TT;
    float k0 = ksyn[n];
    float c0 = 0.075f * k0 / (20.0f - 2.0f * k0);
    g_q[0][idx] = 0.3125f - c0 * __saturatef(u0[idx]);
    float k1 = ksyn[NN + n];
    float c1 = 0.075f * k1 / (20.0f - 2.0f * k1);
    g_q[1][idx] = 0.3125f - c1 * __saturatef(u1[idx]);
}

// One cell's 256-step chunk: compose 8 steps per lane, 2-level truncated shfl
// scan (window 32 steps; dropped terms <= 0.625^32 ~ 2.9e-7), replay + store.
__device__ __forceinline__ void cell_chunk8(
    const float4 xa, const float4 xb, const float4 ya, const float4 yb,
    const bool act, const bool act2, const int lane,
    float& carry, float* __restrict__ o, const int t)
{
    float a0, a1, a2, a3, a4, a5, a6, a7, A, B;
    if (act) {
        a0 = xa.x + ya.x;  a1 = xa.y + ya.y;  a2 = xa.z + ya.z;  a3 = xa.w + ya.w;
        a4 = xb.x + yb.x;  a5 = xb.y + yb.y;  a6 = xb.z + yb.z;  a7 = xb.w + yb.w;
        A = a0; B = fmaf(-20.0f, a0, 12.5f);
        B = fmaf(a1, B, fmaf(-20.0f, a1, 12.5f)); A *= a1;
        B = fmaf(a2, B, fmaf(-20.0f, a2, 12.5f)); A *= a2;
        B = fmaf(a3, B, fmaf(-20.0f, a3, 12.5f)); A *= a3;
        B = fmaf(a4, B, fmaf(-20.0f, a4, 12.5f)); A *= a4;
        B = fmaf(a5, B, fmaf(-20.0f, a5, 12.5f)); A *= a5;
        B = fmaf(a6, B, fmaf(-20.0f, a6, 12.5f)); A *= a6;
        B = fmaf(a7, B, fmaf(-20.0f, a7, 12.5f)); A *= a7;
    } else {
        A = 1.0f; B = 0.0f;
        a0 = a1 = a2 = a3 = a4 = a5 = a6 = a7 = 1.0f;
    }

    // 2-level truncated inclusive scan (window = 4 lanes = 32 steps)
    #pragma unroll
    for (int d = 1; d <= 2; d <<= 1) {
        float Au = __shfl_up_sync(0xffffffffu, A, d);
        float Bu = __shfl_up_sync(0xffffffffu, B, d);
        if (lane >= d) { B = fmaf(A, Bu, B); A *= Au; }
    }

    float Ae = __shfl_up_sync(0xffffffffu, A, 1);
    float Be = __shfl_up_sync(0xffffffffu, B, 1);
    float v = (lane == 0) ? carry : fmaf(Ae, carry, Be);

    float Al = __shfl_sync(0xffffffffu, A, 31);
    float Bl = __shfl_sync(0xffffffffu, B, 31);
    carry = fmaf(Al, carry, Bl);

    if (act) {
        float4 r;
        v = fmaf(a0, v, fmaf(-20.0f, a0, 12.5f)); r.x = v;
        v = fmaf(a1, v, fmaf(-20.0f, a1, 12.5f)); r.y = v;
        v = fmaf(a2, v, fmaf(-20.0f, a2, 12.5f)); r.z = v;
        v = fmaf(a3, v, fmaf(-20.0f, a3, 12.5f)); r.w = v;
        *(float4*)(o + t) = r;
        if (act2) {
            v = fmaf(a4, v, fmaf(-20.0f, a4, 12.5f)); r.x = v;
            v = fmaf(a5, v, fmaf(-20.0f, a5, 12.5f)); r.y = v;
            v = fmaf(a6, v, fmaf(-20.0f, a6, 12.5f)); r.z = v;
            v = fmaf(a7, v, fmaf(-20.0f, a7, 12.5f)); r.w = v;
            *(float4*)(o + t + 4) = r;
        }
    }
}

// Warp owns a 2x2 cell tile: 4 row-loads feed 4 cell-chunks.
// Block = 8 warps covering 4(i) x 8(j) cells; grid 32x64 = 2048 blocks.
__global__ __launch_bounds__(256, 3) void sim_kernel(float* __restrict__ out) {
    const int lane = threadIdx.x & 31;
    const int w    = threadIdx.x >> 5;             // 0..7
    const int i0 = blockIdx.y * 4 + (w >> 2) * 2;
    const int j0 = blockIdx.x * 8 + (w & 3) * 2;

    const float* __restrict__ qi0 = g_q[0] + i0 * TT;
    const float* __restrict__ qi1 = qi0 + TT;
    const float* __restrict__ qj0 = g_q[1] + j0 * TT;
    const float* __restrict__ qj1 = qj0 + TT;

    float* __restrict__ o00 = out + (i0 * NN + j0) * TT;
    float* __restrict__ o01 = o00 + TT;
    float* __restrict__ o10 = o00 + NN * TT;
    float* __restrict__ o11 = o10 + TT;

    float c00 = 0.0f, c01 = 0.0f, c10 = 0.0f, c11 = 0.0f;

    #pragma unroll 1
    for (int c = 0; c < NCHUNK; c++) {
        const int t = c * CT + lane * R;
        const bool act  = (t < TT);
        const bool act2 = (t + R <= TT);

        float4 x0a, x0b, x1a, x1b, y0a, y0b, y1a, y1b;
        if (act) {
            x0a = *(const float4*)(qi0 + t);  x0b = *(const float4*)(qi0 + t + 4);
            x1a = *(const float4*)(qi1 + t);  x1b = *(const float4*)(qi1 + t + 4);
            y0a = *(const float4*)(qj0 + t);  y0b = *(const float4*)(qj0 + t + 4);
            y1a = *(const float4*)(qj1 + t);  y1b = *(const float4*)(qj1 + t + 4);
        }

        cell_chunk8(x0a, x0b, y0a, y0b, act, act2, lane, c00, o00, t);
        cell_chunk8(x0a, x0b, y1a, y1b, act, act2, lane, c01, o01, t);
        cell_chunk8(x1a, x1b, y0a, y0b, act, act2, lane, c10, o10, t);
        cell_chunk8(x1a, x1b, y1a, y1b, act, act2, lane, c11, o11, t);
    }
}

extern "C" void kernel_launch(void* const* d_in, const int* in_sizes, int n_in,
                              void* d_out, int out_size) {
    const float* u0   = (const float*)d_in[0];   // u_pre_0 (N,T)
    const float* u1   = (const float*)d_in[1];   // u_pre_1 (N,T)
    const float* ksyn = (const float*)d_in[2];   // k_syn (2,N)
    float* out = (float*)d_out;                  // (N,N,T) fp32

    prep_kernel<<<(NN * TT + 255) / 256, 256>>>(u0, u1, ksyn);

    dim3 grid(NN / 8, NN / 4);                   // 32 x 64 = 2048 blocks
    sim_kernel<<<grid, 256>>>(out);
}

// round 8
// speedup vs baseline: 1.0772x; 1.0176x over previous
#include <cuda_runtime.h>

#define NN 256
#define TT 1500
#define R 8
#define CT (32 * R)                  // 256 steps per warp-chunk
#define NCHUNK ((TT + CT - 1) / CT)  // 6 (tail chunk: 220 steps)

// q[s][n][t] = 0.3125 - 0.075*g_max[s][n]*sat(u_s[n][t]); a_ij(t) = q0+q1.
// +8 pad: tail lane 27 over-reads 4 floats past the last row (never stored).
__device__ float g_q[2][NN * TT + 8];

__global__ __launch_bounds__(256) void prep_kernel(const float* __restrict__ u0,
                                                   const float* __restrict__ u1,
                                                   const float* __restrict__ ksyn) {
    int idx = blockIdx.x * 256 + threadIdx.x;
    if (idx >= NN * TT) return;
    int n = idx / TT;
    float k0 = ksyn[n];
    float c0 = 0.075f * k0 / (20.0f - 2.0f * k0);
    g_q[0][idx] = 0.3125f - c0 * __saturatef(u0[idx]);
    float k1 = ksyn[NN + n];
    float c1 = 0.075f * k1 / (20.0f - 2.0f * k1);
    g_q[1][idx] = 0.3125f - c1 * __saturatef(u1[idx]);
}

// One cell per warp, R=8 steps per lane per chunk, 2-level truncated shfl scan
// (window 32 steps; dropped terms <= 0.625^32 ~ 3e-7), replay + streaming store.
__global__ __launch_bounds__(512) void sim_kernel(float* __restrict__ out) {
    const int lane = threadIdx.x & 31;
    const int w    = threadIdx.x >> 5;      // 0..15
    const int i = blockIdx.y * 4 + (w >> 2);
    const int j = blockIdx.x * 4 + (w & 3);

    const float* __restrict__ q0 = g_q[0] + i * TT;
    const float* __restrict__ q1 = g_q[1] + j * TT;
    float* __restrict__ o = out + (i * NN + j) * TT;

    float carry = 0.0f;                      // v0 = E_REST = 0

    #pragma unroll 1
    for (int c = 0; c < NCHUNK; c++) {
        const int t = c * CT + lane * R;
        const bool act  = (t < TT);          // first float4 valid
        const bool act2 = (t + R <= TT);     // second float4 valid

        float a0, a1, a2, a3, a4, a5, a6, a7, A, B;
        if (act) {
            float4 xa = *(const float4*)(q0 + t);
            float4 ya = *(const float4*)(q1 + t);
            float4 xb = *(const float4*)(q0 + t + 4);
            float4 yb = *(const float4*)(q1 + t + 4);
            a0 = xa.x + ya.x;  a1 = xa.y + ya.y;  a2 = xa.z + ya.z;  a3 = xa.w + ya.w;
            a4 = xb.x + yb.x;  a5 = xb.y + yb.y;  a6 = xb.z + yb.z;  a7 = xb.w + yb.w;
            A = a0; B = fmaf(-20.0f, a0, 12.5f);
            B = fmaf(a1, B, fmaf(-20.0f, a1, 12.5f)); A *= a1;
            B = fmaf(a2, B, fmaf(-20.0f, a2, 12.5f)); A *= a2;
            B = fmaf(a3, B, fmaf(-20.0f, a3, 12.5f)); A *= a3;
            B = fmaf(a4, B, fmaf(-20.0f, a4, 12.5f)); A *= a4;
            B = fmaf(a5, B, fmaf(-20.0f, a5, 12.5f)); A *= a5;
            B = fmaf(a6, B, fmaf(-20.0f, a6, 12.5f)); A *= a6;
            B = fmaf(a7, B, fmaf(-20.0f, a7, 12.5f)); A *= a7;
        } else {
            A = 1.0f; B = 0.0f;
            a0 = a1 = a2 = a3 = a4 = a5 = a6 = a7 = 1.0f;
        }

        // 2-level truncated inclusive scan (window = 4 lanes = 32 steps)
        #pragma unroll
        for (int d = 1; d <= 2; d <<= 1) {
            float Au = __shfl_up_sync(0xffffffffu, A, d);
            float Bu = __shfl_up_sync(0xffffffffu, B, d);
            if (lane >= d) { B = fmaf(A, Bu, B); A *= Au; }
        }

        // exclusive prefix = inclusive of lane-1; lane 0 takes the chunk carry
        float Ae = __shfl_up_sync(0xffffffffu, A, 1);
        float Be = __shfl_up_sync(0xffffffffu, B, 1);
        float v = (lane == 0) ? carry : fmaf(Ae, carry, Be);

        // chunk carry from lane 31 (window covers 32 steps back)
        float Al = __shfl_sync(0xffffffffu, A, 31);
        float Bl = __shfl_sync(0xffffffffu, B, 31);
        carry = fmaf(Al, carry, Bl);

        if (act) {
            float4 r;
            v = fmaf(a0, v, fmaf(-20.0f, a0, 12.5f)); r.x = v;
            v = fmaf(a1, v, fmaf(-20.0f, a1, 12.5f)); r.y = v;
            v = fmaf(a2, v, fmaf(-20.0f, a2, 12.5f)); r.z = v;
            v = fmaf(a3, v, fmaf(-20.0f, a3, 12.5f)); r.w = v;
            __stcs((float4*)(o + t), r);
            if (act2) {
                v = fmaf(a4, v, fmaf(-20.0f, a4, 12.5f)); r.x = v;
                v = fmaf(a5, v, fmaf(-20.0f, a5, 12.5f)); r.y = v;
                v = fmaf(a6, v, fmaf(-20.0f, a6, 12.5f)); r.z = v;
                v = fmaf(a7, v, fmaf(-20.0f, a7, 12.5f)); r.w = v;
                __stcs((float4*)(o + t + 4), r);
            }
        }
    }
}

extern "C" void kernel_launch(void* const* d_in, const int* in_sizes, int n_in,
                              void* d_out, int out_size) {
    const float* u0   = (const float*)d_in[0];   // u_pre_0 (N,T)
    const float* u1   = (const float*)d_in[1];   // u_pre_1 (N,T)
    const float* ksyn = (const float*)d_in[2];   // k_syn (2,N)
    float* out = (float*)d_out;                  // (N,N,T) fp32

    prep_kernel<<<(NN * TT + 255) / 256, 256>>>(u0, u1, ksyn);

    dim3 grid(NN / 4, NN / 4);                   // 64 x 64 blocks, 512 thr
    sim_kernel<<<grid, 512>>>(out);
}

// round 9
// speedup vs baseline: 1.4767x; 1.3709x over previous
#include <cuda_runtime.h>

#define NN 256
#define TT 1500
#define R 4
#define CT (32 * R)                  // 128 steps per warp-chunk
#define NCHUNK ((TT + CT - 1) / CT)  // 12 (tail chunk: lanes 0..22 active)

// q[s][n][t] = 0.3125 - 0.075*g_max[s][n]*sat(u_s[n][t]); a_ij(t) = q0+q1
__device__ __align__(16) float g_q[2][NN * TT];

__global__ __launch_bounds__(256) void prep_kernel(const float* __restrict__ u0,
                                                   const float* __restrict__ u1,
                                                   const float* __restrict__ ksyn) {
    int g = blockIdx.x * 256 + threadIdx.x;      // float4 index
    if (g >= NN * TT / 4) return;
    int n = (g * 4) / TT;                        // TT%4==0 -> all 4 in same row

    float k0 = ksyn[n];
    float c0 = 0.075f * k0 / (20.0f - 2.0f * k0);
    float4 a = ((const float4*)u0)[g];
    float4 r0;
    r0.x = fmaf(-c0, __saturatef(a.x), 0.3125f);
    r0.y = fmaf(-c0, __saturatef(a.y), 0.3125f);
    r0.z = fmaf(-c0, __saturatef(a.z), 0.3125f);
    r0.w = fmaf(-c0, __saturatef(a.w), 0.3125f);
    ((float4*)g_q[0])[g] = r0;

    float k1 = ksyn[NN + n];
    float c1 = 0.075f * k1 / (20.0f - 2.0f * k1);
    float4 b = ((const float4*)u1)[g];
    float4 r1;
    r1.x = fmaf(-c1, __saturatef(b.x), 0.3125f);
    r1.y = fmaf(-c1, __saturatef(b.y), 0.3125f);
    r1.z = fmaf(-c1, __saturatef(b.z), 0.3125f);
    r1.w = fmaf(-c1, __saturatef(b.w), 0.3125f);
    ((float4*)g_q[1])[g] = r1;
}

// One cell's 128-step chunk. Carry-baked truncated scan (7 shfl):
// lane0 folds carry into its local map; inclusive B_l == v at end of lane l.
// Window = 8 lanes = 32 steps; dropped terms <= 0.625^32 ~ 3e-7.
__device__ __forceinline__ void cell_chunk(const float4 x, const float4 y,
                                           const bool act, const int lane,
                                           float& carry, float* __restrict__ o,
                                           const int t) {
    float a0, a1, a2, a3, A, B;
    if (act) {
        a0 = x.x + y.x;  a1 = x.y + y.y;  a2 = x.z + y.z;  a3 = x.w + y.w;
        A = a0; B = fmaf(-20.0f, a0, 12.5f);
        B = fmaf(a1, B, fmaf(-20.0f, a1, 12.5f)); A *= a1;
        B = fmaf(a2, B, fmaf(-20.0f, a2, 12.5f)); A *= a2;
        B = fmaf(a3, B, fmaf(-20.0f, a3, 12.5f)); A *= a3;
    } else {
        A = 1.0f; B = 0.0f;
        a0 = a1 = a2 = a3 = 1.0f;
    }

    // bake chunk carry into lane 0's map
    if (lane == 0) B = fmaf(A, carry, B);

    // truncated scan; last level needs B only (A dead afterwards)
    float Au, Bu;
    Au = __shfl_up_sync(0xffffffffu, A, 1);
    Bu = __shfl_up_sync(0xffffffffu, B, 1);
    if (lane >= 1) { B = fmaf(A, Bu, B); A *= Au; }
    Au = __shfl_up_sync(0xffffffffu, A, 2);
    Bu = __shfl_up_sync(0xffffffffu, B, 2);
    if (lane >= 2) { B = fmaf(A, Bu, B); A *= Au; }
    Bu = __shfl_up_sync(0xffffffffu, B, 4);
    if (lane >= 4) { B = fmaf(A, Bu, B); }

    // v at start of this lane's segment = B of lane-1 (lane0: carry)
    float vs = __shfl_up_sync(0xffffffffu, B, 1);
    float v = (lane == 0) ? carry : vs;

    // next chunk's carry = v at end of lane 31
    carry = __shfl_sync(0xffffffffu, B, 31);

    if (act) {
        float4 r;
        v = fmaf(a0, v, fmaf(-20.0f, a0, 12.5f)); r.x = v;
        v = fmaf(a1, v, fmaf(-20.0f, a1, 12.5f)); r.y = v;
        v = fmaf(a2, v, fmaf(-20.0f, a2, 12.5f)); r.z = v;
        v = fmaf(a3, v, fmaf(-20.0f, a3, 12.5f)); r.w = v;
        *(float4*)(o + t) = r;
    }
}

// Warp owns cells (i,j0) and (i,j0+1): one q0-row load feeds both.
// Block = 8 warps = 2(i) x 4(j-pairs); grid 32 x 128.
__global__ __launch_bounds__(256) void sim_kernel(float* __restrict__ out) {
    const int lane = threadIdx.x & 31;
    const int w    = threadIdx.x >> 5;             // 0..7
    const int i  = blockIdx.y * 2 + (w >> 2);
    const int j0 = blockIdx.x * 8 + (w & 3) * 2;

    const float* __restrict__ q0 = g_q[0] + i * TT;
    const float* __restrict__ qa = g_q[1] + j0 * TT;
    const float* __restrict__ qb = qa + TT;

    float* __restrict__ oa = out + (i * NN + j0) * TT;
    float* __restrict__ ob = oa + TT;

    float ca = 0.0f, cb = 0.0f;                    // v0 = E_REST = 0

    #pragma unroll 1
    for (int c = 0; c < NCHUNK; c++) {
        const int t = c * CT + lane * R;
        const bool act = (t < TT);

        float4 x, ya, yb;
        if (act) {
            x  = *(const float4*)(q0 + t);
            ya = *(const float4*)(qa + t);
            yb = *(const float4*)(qb + t);
        }

        cell_chunk(x, ya, act, lane, ca, oa, t);
        cell_chunk(x, yb, act, lane, cb, ob, t);
    }
}

extern "C" void kernel_launch(void* const* d_in, const int* in_sizes, int n_in,
                              void* d_out, int out_size) {
    const float* u0   = (const float*)d_in[0];   // u_pre_0 (N,T)
    const float* u1   = (const float*)d_in[1];   // u_pre_1 (N,T)
    const float* ksyn = (const float*)d_in[2];   // k_syn (2,N)
    float* out = (float*)d_out;                  // (N,N,T) fp32

    prep_kernel<<<(NN * TT / 4 + 255) / 256, 256>>>(u0, u1, ksyn);

    dim3 grid(NN / 8, NN / 2);                   // 32 x 128 = 4096 blocks
    sim_kernel<<<grid, 256>>>(out);
}